// round 1
// baseline (speedup 1.0000x reference)
#include <cuda_runtime.h>

// OrthonormalWaveletRegularization: L=32, scalar output.
// One warp does everything: shuffle reductions + tiny per-lane serial loops.

#define SQRT2 1.41421356237309504880

__global__ void owr_kernel(const float* __restrict__ h,
                           const float* __restrict__ g,
                           float* __restrict__ out) {
    const int t = threadIdx.x;            // 0..31
    __shared__ float sh[32];
    __shared__ float sg[32];

    const float hv = h[t];
    const float gv = g[t];
    sh[t] = hv;
    sg[t] = gv;
    __syncwarp();

    // --- sum(h), sum(g), dot(h,h) via butterfly reduction ---
    float s_h = hv, s_g = gv, s_hh = hv * hv;
    #pragma unroll
    for (int o = 16; o > 0; o >>= 1) {
        s_h  += __shfl_xor_sync(0xFFFFFFFFu, s_h,  o);
        s_g  += __shfl_xor_sync(0xFFFFFFFFu, s_g,  o);
        s_hh += __shfl_xor_sync(0xFFFFFFFFu, s_hh, o);
    }
    // all lanes now hold the full sums

    // --- l4: even-shift autocorrelation, lane k = 1..15 handles lag 2k ---
    float lag_sq = 0.0f;
    if (t >= 1 && t <= 15) {
        const int d = 2 * t;
        float acc = 0.0f;
        for (int i = 0; i + d < 32; ++i)
            acc = fmaf(sh[i], sh[i + d], acc);
        lag_sq = acc * acc;
    }
    float l4 = lag_sq;
    #pragma unroll
    for (int o = 16; o > 0; o >>= 1)
        l4 += __shfl_xor_sync(0xFFFFFFFFu, l4, o);

    // --- l5: vanishing moments, lane p = 1..16 ---
    // moment_p = sum_r r^(p-1) * g[r]; term = (moment_p * sqrt2 / 2^p)^2
    double mterm = 0.0;
    if (t >= 1 && t <= 16) {
        const double pm1 = (double)(t - 1);
        double acc = 0.0;
        #pragma unroll 4
        for (int r = 0; r < 32; ++r) {
            // pow(0,0) == 1.0 matches numpy 0**0 for the p=1 row
            acc += pow((double)r, pm1) * (double)sg[r];
        }
        const double norm = SQRT2 / exp2((double)t);
        const double m = acc * norm;
        mterm = m * m;
    }
    double l5 = mterm;
    #pragma unroll
    for (int o = 16; o > 0; o >>= 1)
        l5 += __shfl_xor_sync(0xFFFFFFFFu, l5, o);

    if (t == 0) {
        const double l1 = ((double)s_h - SQRT2) * ((double)s_h - SQRT2);
        const double l2 = (double)s_g * (double)s_g;
        const double l3 = ((double)s_hh - 1.0) * ((double)s_hh - 1.0);
        const double loss = (l1 + l2) + ((double)l3 + (double)l4) + l5;
        out[0] = (float)loss;
    }
}

extern "C" void kernel_launch(void* const* d_in, const int* in_sizes, int n_in,
                              void* d_out, int out_size) {
    const float* h = (const float*)d_in[0];
    const float* g = (const float*)d_in[1];
    float* out = (float*)d_out;
    owr_kernel<<<1, 32>>>(h, g, out);
}

// round 2
// speedup vs baseline: 10.8244x; 10.8244x over previous
#include <cuda_runtime.h>

// OrthonormalWaveletRegularization: L=32, scalar output.
// One warp, all-fp32, compile-time constant power table (kills the 90us
// double-precision pow() tail that dominated R1).

#define SQRT2F 1.41421356237309504880f
#define SQRT2D 1.41421356237309504880

// powers[p][r] = r^p for p = 0..15 (lane t=p+1 uses exponent p = t-1),
// computed exactly in double at compile time, rounded to float.
struct PowTable { float v[16][32]; };

__host__ __device__ constexpr PowTable make_pow_table() {
    PowTable t{};
    for (int p = 0; p < 16; ++p) {
        for (int r = 0; r < 32; ++r) {
            double acc = 1.0;                 // r^0 = 1 (incl. 0^0 = 1, matches numpy)
            for (int e = 0; e < p; ++e) acc *= (double)r;
            t.v[p][r] = (float)acc;
        }
    }
    return t;
}

__constant__ PowTable POWTBL = make_pow_table();

__global__ void owr_kernel(const float* __restrict__ h,
                           const float* __restrict__ g,
                           float* __restrict__ out) {
    const int t = threadIdx.x;            // 0..31
    __shared__ float sh[32];
    __shared__ float sg[32];

    const float hv = h[t];
    const float gv = g[t];
    sh[t] = hv;
    sg[t] = gv;
    __syncwarp();

    // --- sum(h), sum(g), dot(h,h) via butterfly reduction ---
    float s_h = hv, s_g = gv, s_hh = hv * hv;
    #pragma unroll
    for (int o = 16; o > 0; o >>= 1) {
        s_h  += __shfl_xor_sync(0xFFFFFFFFu, s_h,  o);
        s_g  += __shfl_xor_sync(0xFFFFFFFFu, s_g,  o);
        s_hh += __shfl_xor_sync(0xFFFFFFFFu, s_hh, o);
    }

    // --- l4: even-shift autocorrelation, lane k = 1..15 handles lag 2k ---
    float lag_sq = 0.0f;
    if (t >= 1 && t <= 15) {
        const int d = 2 * t;
        float acc = 0.0f;
        for (int i = 0; i + d < 32; ++i)
            acc = fmaf(sh[i], sh[i + d], acc);
        lag_sq = acc * acc;
    }
    float l4 = lag_sq;
    #pragma unroll
    for (int o = 16; o > 0; o >>= 1)
        l4 += __shfl_xor_sync(0xFFFFFFFFu, l4, o);

    // --- l5: vanishing moments, lane t = p = 1..16, exponent p-1 = t-1 ---
    float mterm = 0.0f;
    if (t >= 1 && t <= 16) {
        const float* row = POWTBL.v[t - 1];
        float acc = 0.0f;
        #pragma unroll
        for (int r = 0; r < 32; ++r)
            acc = fmaf(row[r], sg[r], acc);
        const float norm = ldexpf(SQRT2F, -t);   // sqrt2 / 2^p
        const float m = acc * norm;
        mterm = m * m;
    }
    float l5 = mterm;
    #pragma unroll
    for (int o = 16; o > 0; o >>= 1)
        l5 += __shfl_xor_sync(0xFFFFFFFFu, l5, o);

    if (t == 0) {
        const double l1 = ((double)s_h - SQRT2D) * ((double)s_h - SQRT2D);
        const double l2 = (double)s_g * (double)s_g;
        const double l3 = ((double)s_hh - 1.0) * ((double)s_hh - 1.0);
        const double loss = (l1 + l2) + (l3 + (double)l4) + (double)l5;
        out[0] = (float)loss;
    }
}

extern "C" void kernel_launch(void* const* d_in, const int* in_sizes, int n_in,
                              void* d_out, int out_size) {
    const float* h = (const float*)d_in[0];
    const float* g = (const float*)d_in[1];
    float* out = (float*)d_out;
    owr_kernel<<<1, 32>>>(h, g, out);
}